// round 9
// baseline (speedup 1.0000x reference)
#include <cuda_runtime.h>
#include <cstdint>

// ---------------------------------------------------------------------------
// Problem dims
// ---------------------------------------------------------------------------
#define T_STEPS 256
#define BATCH   128
#define N_INP   784
#define N_HID   512
#define N_OUT   128
#define M_TOTAL (T_STEPS * BATCH)   // 32768
#define L1STRIDE 160                // u16 slots per input list row
#define L2STRIDE 544                // u16 slots per hidden list row (<=512 actives +16 pad)
#define HWORDS   16                 // 512/32 hidden-mask words per row

// ---------------------------------------------------------------------------
// Scratch globals
// ---------------------------------------------------------------------------
__device__ __align__(128) float    g_wt1[N_INP * N_HID];                // w_hidden^T
__device__ __align__(128) float    g_wt2[N_HID * N_OUT];                // w_out^T
__device__ __align__(128) uint16_t g_list1[(size_t)M_TOTAL * L1STRIDE]; // 10.5 MB
__device__ __align__(128) int      g_cnt1[M_TOTAL];
__device__ __align__(128) uint32_t g_shb[(size_t)M_TOTAL * HWORDS];     // 2 MB
__device__ __align__(128) uint16_t g_list2[(size_t)M_TOTAL * L2STRIDE]; // 35.7 MB
__device__ __align__(128) int      g_cnt2[M_TOTAL];
__device__ __align__(128) float    g_co[(size_t)M_TOTAL * N_OUT];       // 16 MB

// ---------------------------------------------------------------------------
// Weight transposes
// ---------------------------------------------------------------------------
__global__ void prep_wt1_kernel(const float* __restrict__ wh, float* __restrict__ wt1)
{
    int idx = blockIdx.x * blockDim.x + threadIdx.x;     // k*512 + u
    if (idx >= N_INP * N_HID) return;
    int k = idx >> 9, u = idx & 511;
    wt1[idx] = __ldg(wh + (size_t)u * N_INP + k);
}

__global__ void prep_wt2_kernel(const float* __restrict__ wo, float* __restrict__ wt2)
{
    int idx = blockIdx.x * blockDim.x + threadIdx.x;     // k*128 + o
    if (idx >= N_HID * N_OUT) return;
    int k = idx >> 7, o = idx & 127;
    wt2[idx] = __ldg(wo + (size_t)o * N_HID + k);
}

// ---------------------------------------------------------------------------
// Build input active-index lists. One warp per row. Pads 16 entries.
// ---------------------------------------------------------------------------
__global__ void build_list1_kernel(const float* __restrict__ sp,
                                   uint16_t* __restrict__ list, int* __restrict__ cnts)
{
    const int wid  = threadIdx.x >> 5;
    const int lane = threadIdx.x & 31;
    const int row  = blockIdx.x * 8 + wid;

    uint32_t w = 0;
    if (lane < 24) {
        const float4* p = (const float4*)(sp + (size_t)row * N_INP + lane * 32);
#pragma unroll
        for (int j = 0; j < 8; j++) {
            float4 f = p[j];
            w |= (uint32_t)(f.x > 0.5f) << (j * 4 + 0);
            w |= (uint32_t)(f.y > 0.5f) << (j * 4 + 1);
            w |= (uint32_t)(f.z > 0.5f) << (j * 4 + 2);
            w |= (uint32_t)(f.w > 0.5f) << (j * 4 + 3);
        }
    } else if (lane == 24) {
        const float4* p = (const float4*)(sp + (size_t)row * N_INP + 768);
#pragma unroll
        for (int j = 0; j < 4; j++) {                    // inputs 768..783
            float4 f = p[j];
            w |= (uint32_t)(f.x > 0.5f) << (j * 4 + 0);
            w |= (uint32_t)(f.y > 0.5f) << (j * 4 + 1);
            w |= (uint32_t)(f.z > 0.5f) << (j * 4 + 2);
            w |= (uint32_t)(f.w > 0.5f) << (j * 4 + 3);
        }
    }

    int c = __popc(w);
    int incl = c;
#pragma unroll
    for (int d = 1; d < 32; d <<= 1) {
        int n = __shfl_up_sync(0xffffffffu, incl, d);
        if (lane >= d) incl += n;
    }
    int total = __shfl_sync(0xffffffffu, incl, 31);
    if (total > L1STRIDE - 16) total = L1STRIDE - 16;    // safety clamp (never hit)
    int p0 = incl - c;

    uint16_t* lp = list + (size_t)row * L1STRIDE;
    uint32_t m = w;
    int kb = lane * 32;
    while (m) {
        int k = kb + __ffs(m) - 1;
        m &= m - 1;
        if (p0 < L1STRIDE - 16) lp[p0] = (uint16_t)k;
        p0++;
    }
    if (lane < 16) lp[total + lane] = (uint16_t)N_INP;   // pad -> zero weight row
    if (lane == 0) cnts[row] = total;
}

// ---------------------------------------------------------------------------
// Build hidden active-index lists from ballot bitmask. Pads 16 entries.
// ---------------------------------------------------------------------------
__global__ void build_list2_kernel(const uint32_t* __restrict__ mask,
                                   uint16_t* __restrict__ list, int* __restrict__ cnts)
{
    const int wid  = threadIdx.x >> 5;
    const int lane = threadIdx.x & 31;
    const int row  = blockIdx.x * 8 + wid;

    uint32_t w = (lane < HWORDS) ? mask[(size_t)row * HWORDS + lane] : 0u;
    int c = __popc(w);
    int incl = c;
#pragma unroll
    for (int d = 1; d < 32; d <<= 1) {
        int n = __shfl_up_sync(0xffffffffu, incl, d);
        if (lane >= d) incl += n;
    }
    int total = __shfl_sync(0xffffffffu, incl, 31);      // <= 512
    int p0 = incl - c;

    uint16_t* lp = list + (size_t)row * L2STRIDE;
    uint32_t m = w;
    int kb = lane * 32;
    while (m) {
        int k = kb + __ffs(m) - 1;
        m &= m - 1;
        lp[p0++] = (uint16_t)k;
    }
    if (lane < 16) lp[total + lane] = (uint16_t)N_HID;
    if (lane == 0) cnts[row] = total;
}

// ---------------------------------------------------------------------------
// F1: fused sparse GEMM1 + LIF. Grid (8 chunks of 64 units, 16 btiles of 8).
// 256 thr; warp = batch; lane owns units (ub+lane, ub+32+lane) via LDS.64.
// Slab float2[785][32] = 200960 B (row 784 = zeros = pad target).
// 2-deep group ring + cross-t prefetch hides L2 list latency.
// ---------------------------------------------------------------------------
__global__ __launch_bounds__(256)
void f1_kernel(const float* __restrict__ wt1, const uint16_t* __restrict__ list,
               const int* __restrict__ cnts, uint32_t* __restrict__ shb)
{
    extern __shared__ float2 sw[];                       // [785][32]
    const int tid   = threadIdx.x;
    const int wid   = tid >> 5;
    const int lane  = tid & 31;
    const int chunk = blockIdx.x;                        // 0..7
    const int ub    = chunk * 64;

    for (int i = tid; i < (N_INP + 1) * 32; i += 256) {
        int k = i >> 5, l = i & 31;
        sw[i] = (k < N_INP)
              ? make_float2(wt1[(size_t)k * N_HID + ub + l],
                            wt1[(size_t)k * N_HID + ub + 32 + l])
              : make_float2(0.f, 0.f);
    }
    __syncthreads();

    const int b = blockIdx.y * 8 + wid;
    const float Am = (float)(1e-6 * (1.0 / 6e-6));
    const float Cd = (float)(1.0 - 1e-6 * (1.0 / 6e-6));
    float v0 = 0.f, c0 = 0.f, v1 = 0.f, c1 = 0.f;

    int row = b;
    int cnt = (cnts[row] + 7) & ~7;
    const uint4* lp = (const uint4*)(list + (size_t)row * L1STRIDE);
    uint4 g0 = lp[0];                                    // pad guarantees validity
    uint4 g1 = lp[1];

    for (int t = 0; t < T_STEPS; t++) {
        // prefetch next row's control data early
        int nrow = row + BATCH;
        int ncnt = 0;
        uint4 n0 = g0, n1 = g1;
        const uint4* nlp = (const uint4*)(list + (size_t)nrow * L1STRIDE);
        if (t + 1 < T_STEPS) {
            ncnt = cnts[nrow];
            n0 = nlp[0];
            n1 = nlp[1];
        }

        float a0 = 0.f, a1 = 0.f;
        for (int j = 0; j < cnt; j += 8) {
            uint4 cur = g0;
            g0 = g1;
            int g = (j >> 3) + 2;
            g1 = (g * 8 < cnt) ? lp[g] : g1;
#define ACC1(u) { float2 wv = sw[(u) * 32 + lane]; a0 += wv.x; a1 += wv.y; }
            ACC1(cur.x & 0xffffu); ACC1(cur.x >> 16);
            ACC1(cur.y & 0xffffu); ACC1(cur.y >> 16);
            ACC1(cur.z & 0xffffu); ACC1(cur.z >> 16);
            ACC1(cur.w & 0xffffu); ACC1(cur.w >> 16);
#undef ACC1
        }

        // LIF (reference op order)
        v0 = v0 + Am * (c0 - v0);  c0 = c0 * Cd + a0;
        v1 = v1 + Am * (c1 - v1);  c1 = c1 * Cd + a1;
        bool z0 = (v0 - 1.0f) > 0.0f;
        bool z1 = (v1 - 1.0f) > 0.0f;
        uint32_t bb0 = __ballot_sync(0xffffffffu, z0);
        uint32_t bb1 = __ballot_sync(0xffffffffu, z1);
        size_t rb = (size_t)row * HWORDS + chunk * 2;
        if (lane == 0) shb[rb]     = bb0;
        if (lane == 1) shb[rb + 1] = bb1;
        if (z0) v0 = 0.0f;
        if (z1) v1 = 0.0f;

        row = nrow;
        cnt = (ncnt + 7) & ~7;
        lp  = nlp;
        g0  = n0;
        g1  = n1;
    }
}

// ---------------------------------------------------------------------------
// F2: sparse GEMM2. Grid x = chunk(2 of 64 outs) + 2*tslice(4); y = 16 btiles.
// Slab float2[513][32] = 131328 B. Same ring prefetch. No recurrence.
// ---------------------------------------------------------------------------
__global__ __launch_bounds__(256)
void f2_kernel(const float* __restrict__ wt2, const uint16_t* __restrict__ list,
               const int* __restrict__ cnts, float* __restrict__ co)
{
    extern __shared__ float2 sw[];                       // [513][32]
    const int tid   = threadIdx.x;
    const int wid   = tid >> 5;
    const int lane  = tid & 31;
    const int chunk = blockIdx.x & 1;                    // 0..1
    const int ts    = blockIdx.x >> 1;                   // 0..3
    const int ob    = chunk * 64;

    for (int i = tid; i < (N_HID + 1) * 32; i += 256) {
        int k = i >> 5, l = i & 31;
        sw[i] = (k < N_HID)
              ? make_float2(wt2[(size_t)k * N_OUT + ob + l],
                            wt2[(size_t)k * N_OUT + ob + 32 + l])
              : make_float2(0.f, 0.f);
    }
    __syncthreads();

    const int b  = blockIdx.y * 8 + wid;
    const int t0 = ts * (T_STEPS / 4), t1 = t0 + T_STEPS / 4;

    int row = t0 * BATCH + b;
    int cnt = (cnts[row] + 7) & ~7;
    const uint4* lp = (const uint4*)(list + (size_t)row * L2STRIDE);
    uint4 g0 = lp[0];
    uint4 g1 = lp[1];

    for (int t = t0; t < t1; t++) {
        int nrow = row + BATCH;
        int ncnt = 0;
        uint4 n0 = g0, n1 = g1;
        const uint4* nlp = (const uint4*)(list + (size_t)nrow * L2STRIDE);
        if (t + 1 < t1) {
            ncnt = cnts[nrow];
            n0 = nlp[0];
            n1 = nlp[1];
        }

        float a0 = 0.f, a1 = 0.f;
        for (int j = 0; j < cnt; j += 8) {
            uint4 cur = g0;
            g0 = g1;
            int g = (j >> 3) + 2;
            g1 = (g * 8 < cnt) ? lp[g] : g1;
#define ACC2(u) { float2 wv = sw[(u) * 32 + lane]; a0 += wv.x; a1 += wv.y; }
            ACC2(cur.x & 0xffffu); ACC2(cur.x >> 16);
            ACC2(cur.y & 0xffffu); ACC2(cur.y >> 16);
            ACC2(cur.z & 0xffffu); ACC2(cur.z >> 16);
            ACC2(cur.w & 0xffffu); ACC2(cur.w >> 16);
#undef ACC2
        }

        size_t o = (size_t)row * N_OUT + ob;
        co[o + lane]      = a0;
        co[o + 32 + lane] = a1;

        row = nrow;
        cnt = (ncnt + 7) & ~7;
        lp  = nlp;
        g0  = n0;
        g1  = n1;
    }
}

// ---------------------------------------------------------------------------
// LI readout scan
// ---------------------------------------------------------------------------
__global__ void li_kernel(const float* __restrict__ co, float* __restrict__ out)
{
    const int tid = blockIdx.x * blockDim.x + threadIdx.x;   // b*128 + o
    const float Am = (float)(1e-6 * (1.0 / 6e-6));
    const float Cd = (float)(1.0 - 1e-6 * (1.0 / 6e-6));
    float v = 0.0f, cur = 0.0f;
    const int stride = BATCH * N_OUT;

    for (int t0 = 0; t0 < T_STEPS; t0 += 16) {
        float x[16];
#pragma unroll
        for (int u = 0; u < 16; u++)
            x[u] = co[(size_t)(t0 + u) * stride + tid];
#pragma unroll
        for (int u = 0; u < 16; u++) {
            v = v + Am * (cur - v);
            cur = cur * Cd + x[u];
            out[(size_t)(t0 + u) * stride + tid] = v;
        }
    }
}

// ---------------------------------------------------------------------------
// Launch
// ---------------------------------------------------------------------------
extern "C" void kernel_launch(void* const* d_in, const int* in_sizes, int n_in,
                              void* d_out, int out_size)
{
    const float* spikes = (const float*)d_in[0];
    const float* wh     = (const float*)d_in[1];
    const float* wo     = (const float*)d_in[2];
    float*       out    = (float*)d_out;

    float *wt1, *wt2, *co;
    uint16_t *l1, *l2;
    int *c1, *c2;
    uint32_t *shb;
    cudaGetSymbolAddress((void**)&wt1, g_wt1);
    cudaGetSymbolAddress((void**)&wt2, g_wt2);
    cudaGetSymbolAddress((void**)&l1,  g_list1);
    cudaGetSymbolAddress((void**)&c1,  g_cnt1);
    cudaGetSymbolAddress((void**)&shb, g_shb);
    cudaGetSymbolAddress((void**)&l2,  g_list2);
    cudaGetSymbolAddress((void**)&c2,  g_cnt2);
    cudaGetSymbolAddress((void**)&co,  g_co);

    constexpr int SW1 = (N_INP + 1) * 32 * sizeof(float2);   // 200960
    constexpr int SW2 = (N_HID + 1) * 32 * sizeof(float2);   // 131328
    cudaFuncSetAttribute((const void*)f1_kernel, cudaFuncAttributeMaxDynamicSharedMemorySize, SW1);
    cudaFuncSetAttribute((const void*)f2_kernel, cudaFuncAttributeMaxDynamicSharedMemorySize, SW2);

    // preps
    prep_wt1_kernel<<<(N_INP * N_HID + 255) / 256, 256>>>(wh, wt1);
    prep_wt2_kernel<<<(N_HID * N_OUT + 255) / 256, 256>>>(wo, wt2);
    build_list1_kernel<<<M_TOTAL / 8, 256>>>(spikes, l1, c1);

    // fused sparse GEMM1 + LIF
    f1_kernel<<<dim3(8, 16), 256, SW1>>>(wt1, l1, c1, shb);

    // hidden lists + sparse GEMM2 (t-sliced)
    build_list2_kernel<<<M_TOTAL / 8, 256>>>(shb, l2, c2);
    f2_kernel<<<dim3(8, 16), 256, SW2>>>(wt2, l2, c2, co);

    // LI readout
    li_kernel<<<(BATCH * N_OUT) / 256, 256>>>(co, out);
}

// round 10
// speedup vs baseline: 1.9714x; 1.9714x over previous
#include <cuda_runtime.h>
#include <cstdint>

// ---------------------------------------------------------------------------
// Problem dims
// ---------------------------------------------------------------------------
#define T_STEPS 256
#define BATCH   128
#define N_INP   784
#define N_HID   512
#define N_OUT   128
#define M_TOTAL (T_STEPS * BATCH)   // 32768
#define L1STRIDE 160                // u16 slots per input list row (20 uint4 groups)
#define L2STRIDE 544                // u16 slots per hidden list row (68 uint4 groups)
#define HWORDS   16                 // 512/32 hidden-mask words per row

// ---------------------------------------------------------------------------
// Scratch globals
// ---------------------------------------------------------------------------
__device__ __align__(128) float    g_wt1[N_INP * N_HID];                // w_hidden^T
__device__ __align__(128) float    g_wt2[N_HID * N_OUT];                // w_out^T
__device__ __align__(128) uint16_t g_list1[(size_t)M_TOTAL * L1STRIDE]; // 10.5 MB
__device__ __align__(128) int      g_cnt1[M_TOTAL];
__device__ __align__(128) uint32_t g_shb[(size_t)M_TOTAL * HWORDS];     // 2 MB
__device__ __align__(128) uint16_t g_list2[(size_t)M_TOTAL * L2STRIDE]; // 35.7 MB
__device__ __align__(128) int      g_cnt2[M_TOTAL];
__device__ __align__(128) float    g_co[(size_t)M_TOTAL * N_OUT];       // 16 MB

// ---------------------------------------------------------------------------
// Weight transposes
// ---------------------------------------------------------------------------
__global__ void prep_wt1_kernel(const float* __restrict__ wh, float* __restrict__ wt1)
{
    int idx = blockIdx.x * blockDim.x + threadIdx.x;     // k*512 + u
    if (idx >= N_INP * N_HID) return;
    int k = idx >> 9, u = idx & 511;
    wt1[idx] = __ldg(wh + (size_t)u * N_INP + k);
}

__global__ void prep_wt2_kernel(const float* __restrict__ wo, float* __restrict__ wt2)
{
    int idx = blockIdx.x * blockDim.x + threadIdx.x;     // k*128 + o
    if (idx >= N_HID * N_OUT) return;
    int k = idx >> 7, o = idx & 127;
    wt2[idx] = __ldg(wo + (size_t)o * N_HID + k);
}

// ---------------------------------------------------------------------------
// Build input active-index lists. One warp per row. FULLY pads the row with
// the zero-weight index so multi-t interleaved readers never see garbage.
// ---------------------------------------------------------------------------
__global__ void build_list1_kernel(const float* __restrict__ sp,
                                   uint16_t* __restrict__ list, int* __restrict__ cnts)
{
    const int wid  = threadIdx.x >> 5;
    const int lane = threadIdx.x & 31;
    const int row  = blockIdx.x * 8 + wid;

    uint32_t w = 0;
    if (lane < 24) {
        const float4* p = (const float4*)(sp + (size_t)row * N_INP + lane * 32);
#pragma unroll
        for (int j = 0; j < 8; j++) {
            float4 f = p[j];
            w |= (uint32_t)(f.x > 0.5f) << (j * 4 + 0);
            w |= (uint32_t)(f.y > 0.5f) << (j * 4 + 1);
            w |= (uint32_t)(f.z > 0.5f) << (j * 4 + 2);
            w |= (uint32_t)(f.w > 0.5f) << (j * 4 + 3);
        }
    } else if (lane == 24) {
        const float4* p = (const float4*)(sp + (size_t)row * N_INP + 768);
#pragma unroll
        for (int j = 0; j < 4; j++) {                    // inputs 768..783
            float4 f = p[j];
            w |= (uint32_t)(f.x > 0.5f) << (j * 4 + 0);
            w |= (uint32_t)(f.y > 0.5f) << (j * 4 + 1);
            w |= (uint32_t)(f.z > 0.5f) << (j * 4 + 2);
            w |= (uint32_t)(f.w > 0.5f) << (j * 4 + 3);
        }
    }

    int c = __popc(w);
    int incl = c;
#pragma unroll
    for (int d = 1; d < 32; d <<= 1) {
        int n = __shfl_up_sync(0xffffffffu, incl, d);
        if (lane >= d) incl += n;
    }
    int total = __shfl_sync(0xffffffffu, incl, 31);
    if (total > L1STRIDE - 16) total = L1STRIDE - 16;    // safety clamp (never hit)
    int p0 = incl - c;

    uint16_t* lp = list + (size_t)row * L1STRIDE;
    uint32_t m = w;
    int kb = lane * 32;
    while (m) {
        int k = kb + __ffs(m) - 1;
        m &= m - 1;
        if (p0 < L1STRIDE - 16) lp[p0] = (uint16_t)k;
        p0++;
    }
    for (int i = total + lane; i < L1STRIDE; i += 32)
        lp[i] = (uint16_t)N_INP;                         // pad -> zero weight row
    if (lane == 0) cnts[row] = total;
}

// ---------------------------------------------------------------------------
// Build hidden active-index lists from ballot bitmask. Fully pads row.
// ---------------------------------------------------------------------------
__global__ void build_list2_kernel(const uint32_t* __restrict__ mask,
                                   uint16_t* __restrict__ list, int* __restrict__ cnts)
{
    const int wid  = threadIdx.x >> 5;
    const int lane = threadIdx.x & 31;
    const int row  = blockIdx.x * 8 + wid;

    uint32_t w = (lane < HWORDS) ? mask[(size_t)row * HWORDS + lane] : 0u;
    int c = __popc(w);
    int incl = c;
#pragma unroll
    for (int d = 1; d < 32; d <<= 1) {
        int n = __shfl_up_sync(0xffffffffu, incl, d);
        if (lane >= d) incl += n;
    }
    int total = __shfl_sync(0xffffffffu, incl, 31);      // <= 512
    int p0 = incl - c;

    uint16_t* lp = list + (size_t)row * L2STRIDE;
    uint32_t m = w;
    int kb = lane * 32;
    while (m) {
        int k = kb + __ffs(m) - 1;
        m &= m - 1;
        lp[p0++] = (uint16_t)k;
    }
    for (int i = total + lane; i < L2STRIDE; i += 32)
        lp[i] = (uint16_t)N_HID;
    if (lane == 0) cnts[row] = total;
}

// 8 accumulations from one uint4 of packed u16 indices (LDS.64 each)
#define ACC8(U, A, B)                                                 \
    { float2 w_;                                                      \
      w_ = sw[(U.x & 0xffffu) * 32 + lane]; A += w_.x; B += w_.y;     \
      w_ = sw[(U.x >> 16)     * 32 + lane]; A += w_.x; B += w_.y;     \
      w_ = sw[(U.y & 0xffffu) * 32 + lane]; A += w_.x; B += w_.y;     \
      w_ = sw[(U.y >> 16)     * 32 + lane]; A += w_.x; B += w_.y;     \
      w_ = sw[(U.z & 0xffffu) * 32 + lane]; A += w_.x; B += w_.y;     \
      w_ = sw[(U.z >> 16)     * 32 + lane]; A += w_.x; B += w_.y;     \
      w_ = sw[(U.w & 0xffffu) * 32 + lane]; A += w_.x; B += w_.y;     \
      w_ = sw[(U.w >> 16)     * 32 + lane]; A += w_.x; B += w_.y; }

// ---------------------------------------------------------------------------
// F1: fused sparse GEMM1 + LIF, 4 timesteps interleaved per iteration.
// Grid (8 chunks of 64 units, 16 btiles of 8 warps). Warp = batch; lane owns
// units (ub+lane, ub+32+lane). Slab float2[785][32] (row 784 = zeros).
// ---------------------------------------------------------------------------
__global__ __launch_bounds__(256)
void f1_kernel(const float* __restrict__ wt1, const uint16_t* __restrict__ list,
               const int* __restrict__ cnts, uint32_t* __restrict__ shb)
{
    extern __shared__ float2 sw[];                       // [785][32]
    const int tid   = threadIdx.x;
    const int wid   = tid >> 5;
    const int lane  = tid & 31;
    const int chunk = blockIdx.x;                        // 0..7
    const int ub    = chunk * 64;

    for (int i = tid; i < (N_INP + 1) * 32; i += 256) {
        int k = i >> 5, l = i & 31;
        sw[i] = (k < N_INP)
              ? make_float2(wt1[(size_t)k * N_HID + ub + l],
                            wt1[(size_t)k * N_HID + ub + 32 + l])
              : make_float2(0.f, 0.f);
    }
    __syncthreads();

    const int b = blockIdx.y * 8 + wid;
    const float Am = (float)(1e-6 * (1.0 / 6e-6));
    const float Cd = (float)(1.0 - 1e-6 * (1.0 / 6e-6));
    float v0 = 0.f, c0 = 0.f, v1 = 0.f, c1 = 0.f;

    for (int t0 = 0; t0 < T_STEPS; t0 += 4) {
        const uint4* lp[4];
        int cmax = 0;
#pragma unroll
        for (int i = 0; i < 4; i++) {
            int row = (t0 + i) * BATCH + b;
            lp[i] = (const uint4*)(list + (size_t)row * L1STRIDE);
            int cc = cnts[row];
            cmax = cc > cmax ? cc : cmax;
        }
        cmax = (cmax + 7) & ~7;

        uint4 q[4], nx[4];
#pragma unroll
        for (int i = 0; i < 4; i++) { q[i] = lp[i][0]; nx[i] = lp[i][1]; }

        float a[4][2];
#pragma unroll
        for (int i = 0; i < 4; i++) { a[i][0] = 0.f; a[i][1] = 0.f; }

        for (int j = 0; j < cmax; j += 8) {
            int g = (j >> 3) + 2;                        // <= 19, in-bounds (full pad)
#pragma unroll
            for (int i = 0; i < 4; i++) {
                uint4 u = q[i];
                q[i] = nx[i];
                nx[i] = lp[i][g];
                ACC8(u, a[i][0], a[i][1]);
            }
        }

        // LIF: 4 sequential steps (reference op order)
#pragma unroll
        for (int i = 0; i < 4; i++) {
            v0 = v0 + Am * (c0 - v0);  c0 = c0 * Cd + a[i][0];
            v1 = v1 + Am * (c1 - v1);  c1 = c1 * Cd + a[i][1];
            bool z0 = (v0 - 1.0f) > 0.0f;
            bool z1 = (v1 - 1.0f) > 0.0f;
            uint32_t bb0 = __ballot_sync(0xffffffffu, z0);
            uint32_t bb1 = __ballot_sync(0xffffffffu, z1);
            size_t rb = ((size_t)(t0 + i) * BATCH + b) * HWORDS + chunk * 2;
            if (lane == 0) shb[rb]     = bb0;
            if (lane == 1) shb[rb + 1] = bb1;
            if (z0) v0 = 0.0f;
            if (z1) v1 = 0.0f;
        }
    }
}

// ---------------------------------------------------------------------------
// F2: sparse GEMM2, 4-t interleave, no recurrence -> t-sliced.
// Grid x = chunk(2 of 64 outs) + 2*tslice(4); y = 16 btiles of 8 warps.
// Slab float2[513][32].
// ---------------------------------------------------------------------------
__global__ __launch_bounds__(256)
void f2_kernel(const float* __restrict__ wt2, const uint16_t* __restrict__ list,
               const int* __restrict__ cnts, float* __restrict__ co)
{
    extern __shared__ float2 sw[];                       // [513][32]
    const int tid   = threadIdx.x;
    const int wid   = tid >> 5;
    const int lane  = tid & 31;
    const int chunk = blockIdx.x & 1;                    // 0..1
    const int ts    = blockIdx.x >> 1;                   // 0..3
    const int ob    = chunk * 64;

    for (int i = tid; i < (N_HID + 1) * 32; i += 256) {
        int k = i >> 5, l = i & 31;
        sw[i] = (k < N_HID)
              ? make_float2(wt2[(size_t)k * N_OUT + ob + l],
                            wt2[(size_t)k * N_OUT + ob + 32 + l])
              : make_float2(0.f, 0.f);
    }
    __syncthreads();

    const int b  = blockIdx.y * 8 + wid;
    const int t0s = ts * (T_STEPS / 4);

    for (int t0 = t0s; t0 < t0s + T_STEPS / 4; t0 += 4) {
        const uint4* lp[4];
        int cmax = 0;
#pragma unroll
        for (int i = 0; i < 4; i++) {
            int row = (t0 + i) * BATCH + b;
            lp[i] = (const uint4*)(list + (size_t)row * L2STRIDE);
            int cc = cnts[row];
            cmax = cc > cmax ? cc : cmax;
        }
        cmax = (cmax + 7) & ~7;

        uint4 q[4], nx[4];
#pragma unroll
        for (int i = 0; i < 4; i++) { q[i] = lp[i][0]; nx[i] = lp[i][1]; }

        float a[4][2];
#pragma unroll
        for (int i = 0; i < 4; i++) { a[i][0] = 0.f; a[i][1] = 0.f; }

        for (int j = 0; j < cmax; j += 8) {
            int g = (j >> 3) + 2;                        // <= 65, in-bounds (full pad)
#pragma unroll
            for (int i = 0; i < 4; i++) {
                uint4 u = q[i];
                q[i] = nx[i];
                nx[i] = lp[i][g];
                ACC8(u, a[i][0], a[i][1]);
            }
        }

#pragma unroll
        for (int i = 0; i < 4; i++) {
            size_t o = ((size_t)(t0 + i) * BATCH + b) * N_OUT + ob;
            co[o + lane]      = a[i][0];
            co[o + 32 + lane] = a[i][1];
        }
    }
}

// ---------------------------------------------------------------------------
// LI readout scan
// ---------------------------------------------------------------------------
__global__ void li_kernel(const float* __restrict__ co, float* __restrict__ out)
{
    const int tid = blockIdx.x * blockDim.x + threadIdx.x;   // b*128 + o
    const float Am = (float)(1e-6 * (1.0 / 6e-6));
    const float Cd = (float)(1.0 - 1e-6 * (1.0 / 6e-6));
    float v = 0.0f, cur = 0.0f;
    const int stride = BATCH * N_OUT;

    for (int t0 = 0; t0 < T_STEPS; t0 += 16) {
        float x[16];
#pragma unroll
        for (int u = 0; u < 16; u++)
            x[u] = co[(size_t)(t0 + u) * stride + tid];
#pragma unroll
        for (int u = 0; u < 16; u++) {
            v = v + Am * (cur - v);
            cur = cur * Cd + x[u];
            out[(size_t)(t0 + u) * stride + tid] = v;
        }
    }
}

// ---------------------------------------------------------------------------
// Launch
// ---------------------------------------------------------------------------
extern "C" void kernel_launch(void* const* d_in, const int* in_sizes, int n_in,
                              void* d_out, int out_size)
{
    const float* spikes = (const float*)d_in[0];
    const float* wh     = (const float*)d_in[1];
    const float* wo     = (const float*)d_in[2];
    float*       out    = (float*)d_out;

    float *wt1, *wt2, *co;
    uint16_t *l1, *l2;
    int *c1, *c2;
    uint32_t *shb;
    cudaGetSymbolAddress((void**)&wt1, g_wt1);
    cudaGetSymbolAddress((void**)&wt2, g_wt2);
    cudaGetSymbolAddress((void**)&l1,  g_list1);
    cudaGetSymbolAddress((void**)&c1,  g_cnt1);
    cudaGetSymbolAddress((void**)&shb, g_shb);
    cudaGetSymbolAddress((void**)&l2,  g_list2);
    cudaGetSymbolAddress((void**)&c2,  g_cnt2);
    cudaGetSymbolAddress((void**)&co,  g_co);

    constexpr int SW1 = (N_INP + 1) * 32 * sizeof(float2);   // 200960
    constexpr int SW2 = (N_HID + 1) * 32 * sizeof(float2);   // 131328
    cudaFuncSetAttribute((const void*)f1_kernel, cudaFuncAttributeMaxDynamicSharedMemorySize, SW1);
    cudaFuncSetAttribute((const void*)f2_kernel, cudaFuncAttributeMaxDynamicSharedMemorySize, SW2);

    // preps
    prep_wt1_kernel<<<(N_INP * N_HID + 255) / 256, 256>>>(wh, wt1);
    prep_wt2_kernel<<<(N_HID * N_OUT + 255) / 256, 256>>>(wo, wt2);
    build_list1_kernel<<<M_TOTAL / 8, 256>>>(spikes, l1, c1);

    // fused sparse GEMM1 + LIF
    f1_kernel<<<dim3(8, 16), 256, SW1>>>(wt1, l1, c1, shb);

    // hidden lists + sparse GEMM2 (t-sliced)
    build_list2_kernel<<<M_TOTAL / 8, 256>>>(shb, l2, c2);
    f2_kernel<<<dim3(8, 16), 256, SW2>>>(wt2, l2, c2, co);

    // LI readout
    li_kernel<<<(BATCH * N_OUT) / 256, 256>>>(co, out);
}

// round 12
// speedup vs baseline: 2.0222x; 1.0258x over previous
#include <cuda_runtime.h>
#include <cstdint>

// ---------------------------------------------------------------------------
// Problem dims
// ---------------------------------------------------------------------------
#define T_STEPS 256
#define BATCH   128
#define N_INP   784
#define N_HID   512
#define N_OUT   128
#define M_TOTAL (T_STEPS * BATCH)   // 32768
#define L1STRIDE 160                // u32 offset slots per input list row (40 uint4 groups)
#define L2STRIDE 544                // u32 offset slots per hidden list row (136 groups)
#define HWORDS   16                 // 512/32 hidden-mask words per row
#define PADOFF1  (N_INP * 256)      // byte offset of zero row in F1 slab
#define PADOFF2  (N_HID * 256)      // byte offset of zero row in F2 slab

typedef unsigned long long ull;

// ---------------------------------------------------------------------------
// Scratch globals
// ---------------------------------------------------------------------------
__device__ __align__(128) float    g_wt1[N_INP * N_HID];                // w_hidden^T
__device__ __align__(128) float    g_wt2[N_HID * N_OUT];                // w_out^T
__device__ __align__(128) uint32_t g_list1[(size_t)M_TOTAL * L1STRIDE]; // 21 MB (u32 offs)
__device__ __align__(128) int      g_cnt1[M_TOTAL];
__device__ __align__(128) uint32_t g_shb[(size_t)M_TOTAL * HWORDS];     // 2 MB
__device__ __align__(128) uint32_t g_list2[(size_t)M_TOTAL * L2STRIDE]; // 71 MB (u32 offs)
__device__ __align__(128) int      g_cnt2[M_TOTAL];
__device__ __align__(128) float    g_co[(size_t)M_TOTAL * N_OUT];       // 16 MB

// ---------------------------------------------------------------------------
// Weight transposes
// ---------------------------------------------------------------------------
__global__ void prep_wt1_kernel(const float* __restrict__ wh, float* __restrict__ wt1)
{
    int idx = blockIdx.x * blockDim.x + threadIdx.x;     // k*512 + u
    if (idx >= N_INP * N_HID) return;
    int k = idx >> 9, u = idx & 511;
    wt1[idx] = __ldg(wh + (size_t)u * N_INP + k);
}

__global__ void prep_wt2_kernel(const float* __restrict__ wo, float* __restrict__ wt2)
{
    int idx = blockIdx.x * blockDim.x + threadIdx.x;     // k*128 + o
    if (idx >= N_HID * N_OUT) return;
    int k = idx >> 7, o = idx & 127;
    wt2[idx] = __ldg(wo + (size_t)o * N_HID + k);
}

// ---------------------------------------------------------------------------
// Build input active lists as PRE-SCALED u32 byte offsets (k*256).
// One warp per row; fully pads the row with the zero-row offset.
// ---------------------------------------------------------------------------
__global__ void build_list1_kernel(const float* __restrict__ sp,
                                   uint32_t* __restrict__ list, int* __restrict__ cnts)
{
    const int wid  = threadIdx.x >> 5;
    const int lane = threadIdx.x & 31;
    const int row  = blockIdx.x * 8 + wid;

    uint32_t w = 0;
    if (lane < 24) {
        const float4* p = (const float4*)(sp + (size_t)row * N_INP + lane * 32);
#pragma unroll
        for (int j = 0; j < 8; j++) {
            float4 f = p[j];
            w |= (uint32_t)(f.x > 0.5f) << (j * 4 + 0);
            w |= (uint32_t)(f.y > 0.5f) << (j * 4 + 1);
            w |= (uint32_t)(f.z > 0.5f) << (j * 4 + 2);
            w |= (uint32_t)(f.w > 0.5f) << (j * 4 + 3);
        }
    } else if (lane == 24) {
        const float4* p = (const float4*)(sp + (size_t)row * N_INP + 768);
#pragma unroll
        for (int j = 0; j < 4; j++) {                    // inputs 768..783
            float4 f = p[j];
            w |= (uint32_t)(f.x > 0.5f) << (j * 4 + 0);
            w |= (uint32_t)(f.y > 0.5f) << (j * 4 + 1);
            w |= (uint32_t)(f.z > 0.5f) << (j * 4 + 2);
            w |= (uint32_t)(f.w > 0.5f) << (j * 4 + 3);
        }
    }

    int c = __popc(w);
    int incl = c;
#pragma unroll
    for (int d = 1; d < 32; d <<= 1) {
        int n = __shfl_up_sync(0xffffffffu, incl, d);
        if (lane >= d) incl += n;
    }
    int total = __shfl_sync(0xffffffffu, incl, 31);
    if (total > L1STRIDE - 16) total = L1STRIDE - 16;    // safety clamp (never hit)
    int p0 = incl - c;

    uint32_t* lp = list + (size_t)row * L1STRIDE;
    uint32_t m = w;
    int kb = lane * 32;
    while (m) {
        int k = kb + __ffs(m) - 1;
        m &= m - 1;
        if (p0 < L1STRIDE - 16) lp[p0] = (uint32_t)(k * 256);
        p0++;
    }
    for (int i = total + lane; i < L1STRIDE; i += 32)
        lp[i] = (uint32_t)PADOFF1;                       // pad -> zero weight row
    if (lane == 0) cnts[row] = total;
}

// ---------------------------------------------------------------------------
// Build hidden active lists (pre-scaled u32 offsets) from ballot bitmask.
// ---------------------------------------------------------------------------
__global__ void build_list2_kernel(const uint32_t* __restrict__ mask,
                                   uint32_t* __restrict__ list, int* __restrict__ cnts)
{
    const int wid  = threadIdx.x >> 5;
    const int lane = threadIdx.x & 31;
    const int row  = blockIdx.x * 8 + wid;

    uint32_t w = (lane < HWORDS) ? mask[(size_t)row * HWORDS + lane] : 0u;
    int c = __popc(w);
    int incl = c;
#pragma unroll
    for (int d = 1; d < 32; d <<= 1) {
        int n = __shfl_up_sync(0xffffffffu, incl, d);
        if (lane >= d) incl += n;
    }
    int total = __shfl_sync(0xffffffffu, incl, 31);      // <= 512
    int p0 = incl - c;

    uint32_t* lp = list + (size_t)row * L2STRIDE;
    uint32_t m = w;
    int kb = lane * 32;
    while (m) {
        int k = kb + __ffs(m) - 1;
        m &= m - 1;
        lp[p0++] = (uint32_t)(k * 256);
    }
    for (int i = total + lane; i < L2STRIDE; i += 32)
        lp[i] = (uint32_t)PADOFF2;
    if (lane == 0) cnts[row] = total;
}

// Packed fp32x2 accumulate: ACC += slab[off + lane*8] (both units at once)
#define ACCO(OFF, ACC)                                                         \
    { ull w_ = *(const ull*)(swb + (OFF));                                     \
      asm("add.rn.f32x2 %0, %1, %2;" : "=l"(ACC) : "l"(ACC), "l"(w_)); }

// 4 accumulations from one uint4 of pre-scaled offsets
#define ACC4(U, ACC)  { ACCO(U.x, ACC); ACCO(U.y, ACC); ACCO(U.z, ACC); ACCO(U.w, ACC); }

// ---------------------------------------------------------------------------
// F1: fused sparse GEMM1 + LIF, 8 timesteps interleaved.
// Grid (8 chunks of 64 units, 16 btiles of 8 warps). Warp = batch; lane owns
// units (ub+lane, ub+32+lane) as one packed f32x2. Slab float2[785][32].
// ---------------------------------------------------------------------------
__global__ __launch_bounds__(256)
void f1_kernel(const float* __restrict__ wt1, const uint32_t* __restrict__ list,
               const int* __restrict__ cnts, uint32_t* __restrict__ shb)
{
    extern __shared__ float2 sw[];                       // [785][32]
    const int tid   = threadIdx.x;
    const int wid   = tid >> 5;
    const int lane  = tid & 31;
    const int chunk = blockIdx.x;                        // 0..7
    const int ub    = chunk * 64;

    for (int i = tid; i < (N_INP + 1) * 32; i += 256) {
        int k = i >> 5, l = i & 31;
        sw[i] = (k < N_INP)
              ? make_float2(wt1[(size_t)k * N_HID + ub + l],
                            wt1[(size_t)k * N_HID + ub + 32 + l])
              : make_float2(0.f, 0.f);
    }
    __syncthreads();

    const char* swb = (const char*)sw + lane * 8;        // lane-fixed slab base
    const int b = blockIdx.y * 8 + wid;
    const float Am = (float)(1e-6 * (1.0 / 6e-6));
    const float Cd = (float)(1.0 - 1e-6 * (1.0 / 6e-6));
    float v0 = 0.f, c0 = 0.f, v1 = 0.f, c1 = 0.f;

    for (int t0 = 0; t0 < T_STEPS; t0 += 8) {
        const uint4* lp[8];
        int cmax = 0;
#pragma unroll
        for (int i = 0; i < 8; i++) {
            int row = (t0 + i) * BATCH + b;
            lp[i] = (const uint4*)(list + (size_t)row * L1STRIDE);
            int cc = cnts[row];
            cmax = cc > cmax ? cc : cmax;
        }
        int gmax = (cmax + 3) >> 2;                      // groups of 4

        uint4 q[8], nx[8];
        ull acc[8];
#pragma unroll
        for (int i = 0; i < 8; i++) { q[i] = lp[i][0]; nx[i] = lp[i][1]; acc[i] = 0ull; }

        for (int j = 0; j < gmax; j++) {
            int g = j + 2;                               // <= gmax+1 <= 37 < 40 (full pad)
#pragma unroll
            for (int i = 0; i < 8; i++) {
                uint4 u = q[i];
                q[i] = nx[i];
                nx[i] = lp[i][g];
                ACC4(u, acc[i]);
            }
        }

        // LIF: 8 sequential steps (reference op order)
#pragma unroll
        for (int i = 0; i < 8; i++) {
            float a0 = __uint_as_float((uint32_t)(acc[i] & 0xffffffffu));
            float a1 = __uint_as_float((uint32_t)(acc[i] >> 32));
            v0 = v0 + Am * (c0 - v0);  c0 = c0 * Cd + a0;
            v1 = v1 + Am * (c1 - v1);  c1 = c1 * Cd + a1;
            bool z0 = (v0 - 1.0f) > 0.0f;
            bool z1 = (v1 - 1.0f) > 0.0f;
            uint32_t bb0 = __ballot_sync(0xffffffffu, z0);
            uint32_t bb1 = __ballot_sync(0xffffffffu, z1);
            size_t rb = ((size_t)(t0 + i) * BATCH + b) * HWORDS + chunk * 2;
            if (lane == 0) shb[rb]     = bb0;
            if (lane == 1) shb[rb + 1] = bb1;
            if (z0) v0 = 0.0f;
            if (z1) v1 = 0.0f;
        }
    }
}

// ---------------------------------------------------------------------------
// F2: sparse GEMM2, 8-t interleave, t-sliced x4 (no recurrence).
// Grid x = chunk(2 of 64 outs) + 2*tslice(4); y = 16 btiles of 8 warps.
// Slab float2[513][32].
// ---------------------------------------------------------------------------
__global__ __launch_bounds__(256)
void f2_kernel(const float* __restrict__ wt2, const uint32_t* __restrict__ list,
               const int* __restrict__ cnts, float* __restrict__ co)
{
    extern __shared__ float2 sw[];                       // [513][32]
    const int tid   = threadIdx.x;
    const int wid   = tid >> 5;
    const int lane  = tid & 31;
    const int chunk = blockIdx.x & 1;                    // 0..1
    const int ts    = blockIdx.x >> 1;                   // 0..3
    const int ob    = chunk * 64;

    for (int i = tid; i < (N_HID + 1) * 32; i += 256) {
        int k = i >> 5, l = i & 31;
        sw[i] = (k < N_HID)
              ? make_float2(wt2[(size_t)k * N_OUT + ob + l],
                            wt2[(size_t)k * N_OUT + ob + 32 + l])
              : make_float2(0.f, 0.f);
    }
    __syncthreads();

    const char* swb = (const char*)sw + lane * 8;
    const int b   = blockIdx.y * 8 + wid;
    const int t0s = ts * (T_STEPS / 4);

    for (int t0 = t0s; t0 < t0s + T_STEPS / 4; t0 += 8) {
        const uint4* lp[8];
        int cmax = 0;
#pragma unroll
        for (int i = 0; i < 8; i++) {
            int row = (t0 + i) * BATCH + b;
            lp[i] = (const uint4*)(list + (size_t)row * L2STRIDE);
            int cc = cnts[row];
            cmax = cc > cmax ? cc : cmax;
        }
        int gmax = (cmax + 3) >> 2;

        uint4 q[8], nx[8];
        ull acc[8];
#pragma unroll
        for (int i = 0; i < 8; i++) { q[i] = lp[i][0]; nx[i] = lp[i][1]; acc[i] = 0ull; }

        for (int j = 0; j < gmax; j++) {
            int g = j + 2;                               // <= 129 < 136 (full pad)
#pragma unroll
            for (int i = 0; i < 8; i++) {
                uint4 u = q[i];
                q[i] = nx[i];
                nx[i] = lp[i][g];
                ACC4(u, acc[i]);
            }
        }

#pragma unroll
        for (int i = 0; i < 8; i++) {
            size_t o = ((size_t)(t0 + i) * BATCH + b) * N_OUT + ob;
            co[o + lane]      = __uint_as_float((uint32_t)(acc[i] & 0xffffffffu));
            co[o + 32 + lane] = __uint_as_float((uint32_t)(acc[i] >> 32));
        }
    }
}

// ---------------------------------------------------------------------------
// LI readout scan
// ---------------------------------------------------------------------------
__global__ void li_kernel(const float* __restrict__ co, float* __restrict__ out)
{
    const int tid = blockIdx.x * blockDim.x + threadIdx.x;   // b*128 + o
    const float Am = (float)(1e-6 * (1.0 / 6e-6));
    const float Cd = (float)(1.0 - 1e-6 * (1.0 / 6e-6));
    float v = 0.0f, cur = 0.0f;
    const int stride = BATCH * N_OUT;

    for (int t0 = 0; t0 < T_STEPS; t0 += 16) {
        float x[16];
#pragma unroll
        for (int u = 0; u < 16; u++)
            x[u] = co[(size_t)(t0 + u) * stride + tid];
#pragma unroll
        for (int u = 0; u < 16; u++) {
            v = v + Am * (cur - v);
            cur = cur * Cd + x[u];
            out[(size_t)(t0 + u) * stride + tid] = v;
        }
    }
}

// ---------------------------------------------------------------------------
// Launch
// ---------------------------------------------------------------------------
extern "C" void kernel_launch(void* const* d_in, const int* in_sizes, int n_in,
                              void* d_out, int out_size)
{
    const float* spikes = (const float*)d_in[0];
    const float* wh     = (const float*)d_in[1];
    const float* wo     = (const float*)d_in[2];
    float*       out    = (float*)d_out;

    float *wt1, *wt2, *co;
    uint32_t *l1, *l2, *shb;
    int *c1, *c2;
    cudaGetSymbolAddress((void**)&wt1, g_wt1);
    cudaGetSymbolAddress((void**)&wt2, g_wt2);
    cudaGetSymbolAddress((void**)&l1,  g_list1);
    cudaGetSymbolAddress((void**)&c1,  g_cnt1);
    cudaGetSymbolAddress((void**)&shb, g_shb);
    cudaGetSymbolAddress((void**)&l2,  g_list2);
    cudaGetSymbolAddress((void**)&c2,  g_cnt2);
    cudaGetSymbolAddress((void**)&co,  g_co);

    constexpr int SW1 = (N_INP + 1) * 32 * sizeof(float2);   // 200960
    constexpr int SW2 = (N_HID + 1) * 32 * sizeof(float2);   // 131328
    cudaFuncSetAttribute((const void*)f1_kernel, cudaFuncAttributeMaxDynamicSharedMemorySize, SW1);
    cudaFuncSetAttribute((const void*)f2_kernel, cudaFuncAttributeMaxDynamicSharedMemorySize, SW2);

    // preps
    prep_wt1_kernel<<<(N_INP * N_HID + 255) / 256, 256>>>(wh, wt1);
    prep_wt2_kernel<<<(N_HID * N_OUT + 255) / 256, 256>>>(wo, wt2);
    build_list1_kernel<<<M_TOTAL / 8, 256>>>(spikes, l1, c1);

    // fused sparse GEMM1 + LIF
    f1_kernel<<<dim3(8, 16), 256, SW1>>>(wt1, l1, c1, shb);

    // hidden lists + sparse GEMM2 (t-sliced)
    build_list2_kernel<<<M_TOTAL / 8, 256>>>(shb, l2, c2);
    f2_kernel<<<dim3(8, 16), 256, SW2>>>(wt2, l2, c2, co);

    // LI readout
    li_kernel<<<(BATCH * N_OUT) / 256, 256>>>(co, out);
}